// round 9
// baseline (speedup 1.0000x reference)
#include <cuda_runtime.h>
#include <cstdint>

// FactorizedSpectralConv on GB300 — radix-2 + conjugate-pair + reflection folded DFTs.
// B=16, C=64, H=W=128, M0=M1=16.

typedef unsigned long long ull;
#define PI2_OVER_128 0.04908738521234051935f  // 2*pi/128
#define SGN2 0x8000000080000000ULL

// Scratch (device globals; allocation-free rule)
__device__ float2 g_Xf[512 * 1024];   // [m][t*16+b], 4 MB
__device__ float2 g_Y [512 * 1024];   // [m][b*64+c], 4 MB
__device__ float2 g_W [512 * 4096];   // [m][c*64+t], 16 MB (transposed weights)

__device__ __forceinline__ ull pk2(float x, float y) {
    ull r; asm("mov.b64 %0,{%1,%2};" : "=l"(r) : "f"(x), "f"(y)); return r;
}
__device__ __forceinline__ void upk2(ull v, float& x, float& y) {
    asm("mov.b64 {%0,%1},%2;" : "=f"(x), "=f"(y) : "l"(v));
}
__device__ __forceinline__ void fma2(ull& d, ull a, ull b) {
    asm("fma.rn.f32x2 %0,%1,%2,%0;" : "+l"(d) : "l"(a), "l"(b));
}
__device__ __forceinline__ ull add2(ull a, ull b) {
    ull d; asm("add.rn.f32x2 %0,%1,%2;" : "=l"(d) : "l"(a), "l"(b)); return d;
}
__device__ __forceinline__ ull sub2(ull a, ull b) {
    return add2(a, b ^ SGN2);
}

// ---- compile-time trig (double Taylor, |x| <= pi, err ~1e-11) ----
constexpr double PI_D = 3.14159265358979323846264338327950288;
__host__ __device__ constexpr double tsin_(double x) {
    double t = x, s = x, x2 = x * x;
    for (int i = 1; i <= 12; i++) { t *= -x2 / double((2 * i) * (2 * i + 1)); s += t; }
    return s;
}
__host__ __device__ constexpr double tcos_(double x) {
    double t = 1.0, s = 1.0, x2 = x * x;
    for (int i = 1; i <= 12; i++) { t *= -x2 / double((2 * i - 1) * (2 * i)); s += t; }
    return s;
}
__host__ __device__ constexpr float TWC(int w, int k) {   // cos/16384
    int n = (w * k) & 127;
    double x = (2.0 * PI_D * n) / 128.0;
    if (n > 64) x -= 2.0 * PI_D;
    return (float)(tcos_(x) / 16384.0);
}
__host__ __device__ constexpr float TWS(int w, int k) {   // -sin/16384
    int n = (w * k) & 127;
    double x = (2.0 * PI_D * n) / 128.0;
    if (n > 64) x -= 2.0 * PI_D;
    return (float)(-tsin_(x) / 16384.0);
}

// ---- templated phase-A MAC ladder (forward): twiddles as FFMA immediates ----
template <int W, int K = 0>
__device__ __forceinline__ void rowA(float xp, float xm, float* ar, float* ai) {
    if constexpr (K < 16) {
        constexpr float c = TWC(W, K);
        constexpr float s = TWS(W, K);
        float x = (K & 1) ? xm : xp;
        ar[K] = fmaf(x, c, ar[K]);
        ai[K] = fmaf(x, s, ai[K]);
        rowA<W, K + 1>(xp, xm, ar, ai);
    }
}
template <int C0, int W2 = 0>
__device__ __forceinline__ void chunkA(const float2 (*Xs2)[17], int tid,
                                       float* ar, float* ai) {
    if constexpr (W2 < 16) {
        float2 xv = Xs2[tid][W2];
        rowA<C0 + W2>(xv.x + xv.y, xv.x - xv.y, ar, ai);
        chunkA<C0, W2 + 1>(Xs2, tid, ar, ai);
    }
}

// ---------------------------------------------------------------------------
// K0: weight transpose  w[c][t][kx0][ky] (stride-256 cols) -> g_W[m][c*64+t]
// ---------------------------------------------------------------------------
__global__ void __launch_bounds__(256) k_transpose(
    const float* __restrict__ w0r, const float* __restrict__ w0i,
    const float* __restrict__ w1r, const float* __restrict__ w1i) {
    __shared__ float Tr[32][33], Ti[32][33];
    int bid = blockIdx.x;
    int arr = bid >> 10;
    int tix = bid & 1023;
    int ctTile = tix >> 3, mTile = tix & 7;
    const float* Sr = arr ? w1r : w0r;
    const float* Si = arr ? w1i : w0i;
    int tx = threadIdx.x & 31, ty = threadIdx.x >> 5;
    #pragma unroll
    for (int yy = 0; yy < 4; yy++) {
        int r = ty + yy * 8;
        int row = ctTile * 32 + r, col = mTile * 32 + tx;
        Tr[r][tx] = Sr[row * 256 + col];
        Ti[r][tx] = Si[row * 256 + col];
    }
    __syncthreads();
    #pragma unroll
    for (int yy = 0; yy < 4; yy++) {
        int r = ty + yy * 8;
        int m = arr * 256 + mTile * 32 + r;
        int ct = ctTile * 32 + tx;
        g_W[(size_t)m * 4096 + ct] = make_float2(Tr[tx][r], Ti[tx][r]);
    }
}

// ---------------------------------------------------------------------------
// K1: forward. grid = 1024 blocks, 128 threads, Xs2/Fw smem overlay.
// ---------------------------------------------------------------------------
__global__ void __launch_bounds__(128, 8) k_forward(const float* __restrict__ X) {
    __shared__ __align__(16) ull TWB[128][2];   // (c,-s),(s,c) — 2KB
    __shared__ __align__(16) char u_smem[17408];  // Xs2 / Fw overlay
    float2 (*Xs2)[17] = (float2(*)[17])u_smem;
    ull    (*Fw)[129] = (ull(*)[129])u_smem;

    int tid = threadIdx.x;
    {
        float s, c; sincosf(PI2_OVER_128 * (float)tid, &s, &c);
        TWB[tid][0] = pk2(c, -s);
        TWB[tid][1] = pk2(s, c);
    }

    const float* Xp = X + (size_t)blockIdx.x * 16384;

    float ar[16], ai[16];
    #pragma unroll
    for (int k = 0; k < 16; k++) { ar[k] = 0.f; ai[k] = 0.f; }

    #pragma unroll 1
    for (int c0 = 0; c0 < 64; c0 += 16) {
        __syncthreads();
        #pragma unroll
        for (int p = 0; p < 8; p++) {
            int i = p * 128 + tid;
            int r = i >> 3, q = i & 7;
            const float* src = (q < 4) ? (Xp + r * 128 + c0 + q * 4)
                                       : (Xp + r * 128 + c0 + 64 + (q - 4) * 4);
            float4 v = *(const float4*)src;
            if (q < 4) {
                Xs2[r][q * 4 + 0].x = v.x; Xs2[r][q * 4 + 1].x = v.y;
                Xs2[r][q * 4 + 2].x = v.z; Xs2[r][q * 4 + 3].x = v.w;
            } else {
                Xs2[r][(q - 4) * 4 + 0].y = v.x; Xs2[r][(q - 4) * 4 + 1].y = v.y;
                Xs2[r][(q - 4) * 4 + 2].y = v.z; Xs2[r][(q - 4) * 4 + 3].y = v.w;
            }
        }
        __syncthreads();
        switch (c0) {
            case 0:  chunkA<0 >(Xs2, tid, ar, ai); break;
            case 16: chunkA<16>(Xs2, tid, ar, ai); break;
            case 32: chunkA<32>(Xs2, tid, ar, ai); break;
            default: chunkA<48>(Xs2, tid, ar, ai); break;
        }
    }

    __syncthreads();
    #pragma unroll
    for (int k = 0; k < 16; k++) Fw[k][tid] = pk2(ar[k], ai[k]);
    __syncthreads();

    int ky = tid & 15, kxg = tid >> 4;
    ull accB[4] = {0, 0, 0, 0}, accC[4] = {0, 0, 0, 0};
    int kxv[4], idx[4];
    #pragma unroll
    for (int j = 0; j < 4; j++) {
        int kxIdx = kxg * 4 + j;
        kxv[j] = (kxIdx < 16) ? kxIdx : (96 + kxIdx);
        idx[j] = 0;
    }
    for (int h = 0; h < 64; h++) {
        ull a = Fw[ky][h], b = Fw[ky][h + 64];
        ull p = add2(a, b), m = sub2(a, b);
        float pr, pi, mr, mi;
        upk2(p, pr, pi); upk2(m, mr, mi);
        ull prr = pk2(pr, pr), pii = pk2(pi, pi);
        ull mrr = pk2(mr, mr), mii = pk2(mi, mi);
        #pragma unroll
        for (int j = 0; j < 4; j++) {
            ulonglong2 e = *(const ulonglong2*)&TWB[idx[j]][0];
            if (j & 1) { fma2(accB[j], mrr, e.x); fma2(accC[j], mii, e.y); }
            else       { fma2(accB[j], prr, e.x); fma2(accC[j], pii, e.y); }
            idx[j] = (idx[j] + kxv[j]) & 127;
        }
    }
    int b = blockIdx.x >> 6, t = blockIdx.x & 63;
    #pragma unroll
    for (int j = 0; j < 4; j++) {
        int m = (kxg * 4 + j) * 16 + ky;
        ull r = add2(accB[j], accC[j]);
        float re, im; upk2(r, re, im);
        g_Xf[m * 1024 + t * 16 + b] = make_float2(re, im);
    }
}

// ---------------------------------------------------------------------------
// K2: mode mixing. grid = 512, 256 threads. b in lanes -> weights broadcast.
// ---------------------------------------------------------------------------
__global__ void __launch_bounds__(256) k_modes() {
    extern __shared__ __align__(16) char sm2[];
    ulonglong2* Wsp = (ulonglong2*)sm2;                          // [64 t][65]
    ulonglong2* Xsm = (ulonglong2*)(sm2 + 64 * 65 * 16);         // [64 t][16 b]
    ull*        Ys2 = (ull*)(sm2 + 64 * 65 * 16 + 64 * 16 * 16); // [1024]

    int m = blockIdx.x, tid = threadIdx.x;

    #pragma unroll
    for (int p = 0; p < 16; p++) {
        int i = tid + p * 256;
        float2 w = g_W[(size_t)m * 4096 + i];
        Wsp[(i & 63) * 65 + (i >> 6)] = make_ulonglong2(pk2(w.x, w.x), pk2(w.y, w.y));
    }
    #pragma unroll
    for (int p = 0; p < 4; p++) {
        int i = tid + p * 256;
        float2 x = g_Xf[m * 1024 + i];
        Xsm[i] = make_ulonglong2(pk2(x.x, x.y), pk2(-x.y, x.x));
    }
    __syncthreads();

    int b = tid & 15, cq = tid >> 4;
    ull acc[4] = {0, 0, 0, 0};
    for (int t = 0; t < 64; t++) {
        ulonglong2 xv = Xsm[t * 16 + b];
        #pragma unroll
        for (int j = 0; j < 4; j++) {
            ulonglong2 wv = Wsp[t * 65 + cq * 4 + j];
            fma2(acc[j], wv.x, xv.x);
            fma2(acc[j], wv.y, xv.y);
        }
    }
    #pragma unroll
    for (int j = 0; j < 4; j++) Ys2[b * 64 + cq * 4 + j] = acc[j];
    __syncthreads();
    #pragma unroll
    for (int p = 0; p < 4; p++) {
        int i = tid + p * 256;
        *(ull*)&g_Y[(size_t)m * 1024 + i] = Ys2[i];
    }
}

// ---------------------------------------------------------------------------
// K3: inverse. grid = 1024 blocks, 256 threads, <=64 regs.
// Folds: conjugate-pair (kx<->-kx), kx parity (h+64), h reflection (64-h),
//        ky parity (w+64), w reflection (128-w).
// ---------------------------------------------------------------------------
__global__ void __launch_bounds__(256, 4) k_inverse(float* __restrict__ out) {
    __shared__ __align__(16) ulonglong2 TWI2[128];   // ((c,c),(s,s)) — 2KB
    __shared__ __align__(16) ulonglong2 TWIB[128];   // ((2c,2c),(-2s,-2s)) — 2KB
    __shared__ ull Ysm[512];                         // 4KB
    __shared__ __align__(16) ulonglong2 UVs[16][16]; // [n-1][ky] = (U2, W2) — 4KB
    __shared__ ull Y0s[16];
    __shared__ __align__(16) ulonglong2 ZZ[64][17];  // 17.4KB

    int tid = threadIdx.x;
    int off = blockIdx.x;   // b*64 + c
    Ysm[tid]       = *(const ull*)&g_Y[(size_t)tid * 1024 + off];
    Ysm[tid + 256] = *(const ull*)&g_Y[(size_t)(tid + 256) * 1024 + off];
    if (tid < 128) {
        float s, c; sincosf(PI2_OVER_128 * (float)tid, &s, &c);
        TWI2[tid] = make_ulonglong2(pk2(c, c), pk2(s, s));
        TWIB[tid] = make_ulonglong2(pk2(2.f * c, 2.f * c), pk2(-2.f * s, -2.f * s));
    }
    __syncthreads();

    // Build U/V pair data: n=1..15 pairs (kx=n, kx=-n), n=16 single (kx=-16).
    {
        int n = (tid >> 4) + 1, ky = tid & 15;
        ull U2, W2;
        if (n < 16) {
            ull Ya = Ysm[n * 16 + ky], Yb = Ysm[(32 - n) * 16 + ky];
            U2 = add2(Ya, Yb);                 // (Ur, Ui)
            ull D = sub2(Ya, Yb);              // (Vr, Vi)
            float dr, di; upk2(D, dr, di);
            W2 = pk2(-di, dr);                 // (-Vi, Vr)
        } else {
            ull Ya = Ysm[256 + ky];            // Y(-16)
            float yr, yi; upk2(Ya, yr, yi);
            U2 = Ya;                           // (Yr, Yi)
            W2 = pk2(yi, -yr);                 // (Yi, -Yr)
        }
        UVs[n - 1][ky] = make_ulonglong2(U2, W2);
        if (tid < 16) Y0s[tid] = Ysm[tid];
    }
    __syncthreads();

    // Phase A: thread (ky, hc) handles h-classes hc and hc+16; each class
    // yields Z at {q, q+64, 64-q, 128-q} via C/S parity accumulators.
    {
        int ky = tid & 15, hc = tid >> 4;
        ull Y0 = Y0s[ky];
        ull CE1 = Y0, CO1 = 0, SE1 = 0, SO1 = 0;
        ull CE2 = Y0, CO2 = 0, SE2 = 0, SO2 = 0;
        int a1 = hc, a2 = (hc + 16);
        #pragma unroll
        for (int n = 1; n <= 16; n++) {
            ulonglong2 uv = UVs[n - 1][ky];
            ulonglong2 e1 = TWI2[a1];
            ulonglong2 e2 = TWI2[a2];
            if (n & 1) {
                fma2(CO1, uv.x, e1.x); fma2(SO1, uv.y, e1.y);
                fma2(CO2, uv.x, e2.x); fma2(SO2, uv.y, e2.y);
            } else {
                fma2(CE1, uv.x, e1.x); fma2(SE1, uv.y, e1.y);
                fma2(CE2, uv.x, e2.x); fma2(SE2, uv.y, e2.y);
            }
            a1 = (a1 + hc) & 127;
            a2 = (a2 + hc + 16) & 127;
        }
        {   // class q = hc: rows hc and 64-hc
            ull P = add2(CE1, CO1), Q = sub2(CE1, CO1);
            ull R = add2(SE1, SO1), T = sub2(SE1, SO1);
            ull z1 = add2(P, R), z2 = add2(Q, T);   // Z(q), Z(q+64)
            float r1, i1, r2, i2; upk2(z1, r1, i1); upk2(z2, r2, i2);
            ZZ[hc][ky] = make_ulonglong2(pk2(r1, r2), pk2(i1, i2));
            if (hc != 0) {
                ull z3 = sub2(Q, T), z4 = sub2(P, R);   // Z(64-q), Z(128-q)
                float r3, i3, r4, i4; upk2(z3, r3, i3); upk2(z4, r4, i4);
                ZZ[64 - hc][ky] = make_ulonglong2(pk2(r3, r4), pk2(i3, i4));
            }
        }
        {   // class q = hc+16: rows hc+16 and 48-hc
            int q = hc + 16;
            ull P = add2(CE2, CO2), Q = sub2(CE2, CO2);
            ull R = add2(SE2, SO2), T = sub2(SE2, SO2);
            ull z1 = add2(P, R), z2 = add2(Q, T);
            float r1, i1, r2, i2; upk2(z1, r1, i1); upk2(z2, r2, i2);
            ZZ[q][ky] = make_ulonglong2(pk2(r1, r2), pk2(i1, i2));
            ull z3 = sub2(Q, T), z4 = sub2(P, R);
            float r3, i3, r4, i4; upk2(z3, r3, i3); upk2(z4, r4, i4);
            ZZ[64 - q][ky] = make_ulonglong2(pk2(r3, r4), pk2(i3, i4));
        }
        // Row 32 (h=32, h=96): i^n pattern, 16 threads.
        if (tid < 16) {
            int k0 = tid;
            ull C = Y0s[k0], S = 0;
            #pragma unroll
            for (int n = 2; n <= 16; n += 2) {          // cos(n*pi/2) = (-1)^{n/2}
                ull u = UVs[n - 1][k0].x;
                C = ((n >> 1) & 1) ? sub2(C, u) : add2(C, u);
            }
            #pragma unroll
            for (int n = 1; n <= 15; n += 2) {          // sin(n*pi/2) = (-1)^{(n-1)/2}
                ull w = UVs[n - 1][k0].y;
                S = ((n >> 1) & 1) ? sub2(S, w) : add2(S, w);
            }
            ull zA = add2(C, S), zB = sub2(C, S);       // Z(32), Z(96)
            float ra, ia, rb, ib; upk2(zA, ra, ia); upk2(zB, rb, ib);
            ZZ[32][k0] = make_ulonglong2(pk2(ra, rb), pk2(ia, ib));
        }
    }
    __syncthreads();

    // Phase B: thread (wl, rg) -> w in {wl, wl+64, 64-wl, 128-wl}, 8 rows.
    int wl = tid & 31, rg = tid >> 5;
    float* op = out + (size_t)blockIdx.x * 16384;
    #pragma unroll 1
    for (int pass = 0; pass < 2; pass++) {
        int r0 = rg * 8 + pass * 4;
        ull CE[4], CO[4], SE[4], SO[4];
        #pragma unroll
        for (int i = 0; i < 4; i++) {
            CE[i] = ZZ[r0 + i][0].x;   // Re(Z0) pair, weight 1
            CO[i] = 0; SE[i] = 0; SO[i] = 0;
        }
        int a = wl;
        #pragma unroll
        for (int k = 1; k < 16; k++) {
            ulonglong2 e = TWIB[a];
            if (k & 1) {
                #pragma unroll
                for (int i = 0; i < 4; i++) {
                    ulonglong2 zz = ZZ[r0 + i][k];
                    fma2(CO[i], zz.x, e.x);
                    fma2(SO[i], zz.y, e.y);
                }
            } else {
                #pragma unroll
                for (int i = 0; i < 4; i++) {
                    ulonglong2 zz = ZZ[r0 + i][k];
                    fma2(CE[i], zz.x, e.x);
                    fma2(SE[i], zz.y, e.y);
                }
            }
            a = (a + wl) & 127;
        }
        #pragma unroll
        for (int i = 0; i < 4; i++) {
            int r = r0 + i;
            ull P = add2(CE[i], CO[i]), Q = sub2(CE[i], CO[i]);
            ull R = add2(SE[i], SO[i]), T = sub2(SE[i], SO[i]);
            ull o1 = add2(P, R);   // w = wl
            ull o2 = add2(Q, T);   // w = wl + 64
            ull o3 = sub2(Q, T);   // w = 64 - wl
            ull o4 = sub2(P, R);   // w = 128 - wl
            float a1, b1, a2, b2, a3, b3, a4, b4;
            upk2(o1, a1, b1); upk2(o2, a2, b2);
            upk2(o3, a3, b3); upk2(o4, a4, b4);
            op[r * 128 + wl]              = a1;
            op[(r + 64) * 128 + wl]       = b1;
            op[r * 128 + 64 + wl]         = a2;
            op[(r + 64) * 128 + 64 + wl]  = b2;
            op[r * 128 + 64 - wl]         = a3;
            op[(r + 64) * 128 + 64 - wl]  = b3;
            if (wl != 0) {
                op[r * 128 + 128 - wl]            = a4;
                op[(r + 64) * 128 + 128 - wl]     = b4;
            }
        }
    }
    // w = 32 / 96 epilogue: i^k pattern, 64 threads.
    if (tid < 64) {
        int r = tid;
        ull C = ZZ[r][0].x, S = 0;
        #pragma unroll
        for (int k = 2; k <= 14; k += 2) {          // 2*zr*cos(k*pi/2)
            ull v = ZZ[r][k].x;
            ull v2 = add2(v, v);
            C = ((k >> 1) & 1) ? sub2(C, v2) : add2(C, v2);
        }
        #pragma unroll
        for (int k = 1; k <= 15; k += 2) {          // -2*zi*sin(k*pi/2)
            ull v = ZZ[r][k].y;
            ull v2 = add2(v, v);
            S = ((k >> 1) & 1) ? add2(S, v2) : sub2(S, v2);
        }
        ull oA = add2(C, S), oB = sub2(C, S);       // w=32, w=96
        float a1, b1, a2, b2; upk2(oA, a1, b1); upk2(oB, a2, b2);
        op[r * 128 + 32]        = a1;
        op[(r + 64) * 128 + 32] = b1;
        op[r * 128 + 96]        = a2;
        op[(r + 64) * 128 + 96] = b2;
    }
}

// ---------------------------------------------------------------------------
extern "C" void kernel_launch(void* const* d_in, const int* in_sizes, int n_in,
                              void* d_out, int out_size) {
    const float* X   = (const float*)d_in[0];
    const float* w0r = (const float*)d_in[1];
    const float* w0i = (const float*)d_in[2];
    const float* w1r = (const float*)d_in[3];
    const float* w1i = (const float*)d_in[4];
    float* out = (float*)d_out;

    static bool attr_done = false;
    if (!attr_done) {
        cudaFuncSetAttribute(k_modes, cudaFuncAttributeMaxDynamicSharedMemorySize,
                             91136);
        attr_done = true;
    }

    k_transpose<<<2048, 256>>>(w0r, w0i, w1r, w1i);
    k_forward<<<1024, 128>>>(X);
    k_modes<<<512, 256, 91136>>>();
    k_inverse<<<1024, 256>>>(out);
}